// round 16
// baseline (speedup 1.0000x reference)
#include <cuda_runtime.h>
#include <cuda_fp16.h>
#include <cstdint>

#define B_  256
#define C_  384
#define N_  256
#define NH  12
#define HD  32
#define H3  1152

// SCALE * log2(e): fold exp's base-2 conversion into Q normalization
__device__ __constant__ float kQS = 0.25507698105546733f;

// ---------------- scratch (module-load allocated) ----------------
__device__ __half g_Q[B_ * NH * N_ * HD];   // (b,h,n,d) fp16 (pre-norm)
__device__ __half g_K[B_ * NH * N_ * HD];
__device__ __half g_V[B_ * NH * N_ * HD];
__device__ __half g_X[B_ * N_ * C_];        // (b,n,c)
__device__ __half g_AO[B_ * N_ * C_];       // attention out (b,n,c)
__device__ __half g_Wq[H3 * C_];
__device__ __half g_Wp[C_ * C_];

// ---------------- baseline-PTX helpers ----------
__device__ __forceinline__ uint32_t smem_u32(const void* p) {
    uint32_t a;
    asm("{ .reg .u64 t; cvta.to.shared.u64 t, %1; cvt.u32.u64 %0, t; }" : "=r"(a) : "l"(p));
    return a;
}
__device__ __forceinline__ void cp16(uint32_t dst, const void* src) {
    asm volatile("cp.async.cg.shared.global [%0], [%1], 16;" :: "r"(dst), "l"(src));
}
__device__ __forceinline__ void cp_commit() {
    asm volatile("cp.async.commit_group;" ::: "memory");
}
template <int N>
__device__ __forceinline__ void cp_wait() {
    asm volatile("cp.async.wait_group %0;" :: "n"(N) : "memory");
}
__device__ __forceinline__ void ldm_x4(uint32_t* r, uint32_t addr) {
    asm volatile("ldmatrix.sync.aligned.m8n8.x4.shared.b16 {%0,%1,%2,%3}, [%4];"
                 : "=r"(r[0]), "=r"(r[1]), "=r"(r[2]), "=r"(r[3]) : "r"(addr));
}
__device__ __forceinline__ void ldm_x4_t(uint32_t* r, uint32_t addr) {
    asm volatile("ldmatrix.sync.aligned.m8n8.x4.trans.shared.b16 {%0,%1,%2,%3}, [%4];"
                 : "=r"(r[0]), "=r"(r[1]), "=r"(r[2]), "=r"(r[3]) : "r"(addr));
}
__device__ __forceinline__ void mma16816(float* d, const uint32_t* a, uint32_t b0, uint32_t b1) {
    asm volatile("mma.sync.aligned.m16n8k16.row.col.f32.f16.f16.f32 "
                 "{%0,%1,%2,%3}, {%4,%5,%6,%7}, {%8,%9}, {%0,%1,%2,%3};"
                 : "+f"(d[0]), "+f"(d[1]), "+f"(d[2]), "+f"(d[3])
                 : "r"(a[0]), "r"(a[1]), "r"(a[2]), "r"(a[3]), "r"(b0), "r"(b1));
}
__device__ __forceinline__ float ex2f(float x) {
    float y;
    asm("ex2.approx.ftz.f32 %0, %1;" : "=f"(y) : "f"(x));
    return y;
}

// Swizzled tile: 128 rows x 32 halves (64B/row), row-pairs in 128B lines,
// 16B chunks XOR-swizzled -> conflict-free ldmatrix.
__device__ __forceinline__ uint32_t tile_off(int row, int c) {
    return ((row >> 1) << 7) + ((((((row & 1) << 2) | c)) ^ ((row >> 1) & 7)) << 4);
}
__device__ __forceinline__ uint32_t off256(int row, int c) {  // 256-row tile
    return ((row >> 7) << 13) + tile_off(row & 127, c);
}
__device__ __forceinline__ uint32_t pack2h(float a, float b) {
    __half2 h = __floats2half2_rn(a, b);
    return *(uint32_t*)&h;
}

#define ONES2H 0x3C003C00u   // fp16 {1.0, 1.0} — constant all-ones B fragment

// GEMM stage layout: two K32 tiles per stage (A0,B0,A1,B1), 8KB each.
// 3 stages -> cp.async lookahead of 2 compute-stages.
#define OFF_A  0
#define OFF_B  8192
#define HSTEP  16384
#define STAGE  32768
#define NSTG   3
#define SM_TOTAL (NSTG * STAGE)

// ---------------------------------------------------------------------------
// Fused converts: blocks [0, XBLOCKS) transpose+convert x; rest convert weights.
// ---------------------------------------------------------------------------
#define XBLOCKS (B_ * 96)   // 12 c-tiles x 8 n-tiles per b

__global__ __launch_bounds__(256) void convert_all(const float* __restrict__ x,
                                                   const float* __restrict__ qw,
                                                   const float* __restrict__ pw)
{
    if (blockIdx.x < XBLOCKS) {
        __shared__ float tile[32][33];
        const int bid = blockIdx.x;
        const int b = bid / 96, r = bid - b * 96;
        const int c0 = (r % 12) * 32, n0 = (r / 12) * 32;
        const int tx = threadIdx.x & 31, ty = threadIdx.x >> 5;
        const float* xb = x + (size_t)b * C_ * N_;
#pragma unroll
        for (int rr = 0; rr < 4; rr++) {
            int c = ty + rr * 8;
            tile[c][tx] = xb[(size_t)(c0 + c) * N_ + n0 + tx];
        }
        __syncthreads();
#pragma unroll
        for (int rr = 0; rr < 4; rr++) {
            int n = ty + rr * 8;
            size_t o = (size_t)b * N_ * C_ + (size_t)(n0 + n) * C_ + c0 + tx;
            g_X[o] = __float2half_rn(tile[tx][n]);
        }
    } else {
        const int i = (blockIdx.x - XBLOCKS) * 256 + threadIdx.x;
        if (i < H3 * C_) g_Wq[i] = __float2half_rn(qw[i]);
        const int j = i - H3 * C_;
        if (j >= 0 && j < C_ * C_) g_Wp[j] = __float2half_rn(pw[j]);
    }
}

// ---------------------------------------------------------------------------
// HMMA fp16 GEMM:  D[m,o] = sum_c A[m,c]*B[o,c]  (single fp16 operands)
// CTA tile 128x128, stage = 2 x K32 chunks, 3-stage cp.async pipeline
// (2-stage lookahead hides L2/DRAM latency), 8 warps of 32m x 64n.
// MODE 0: A=g_X, B=g_Wq -> +bias, scatter g_Q/K/V (b,h,n,d) fp16
// MODE 1: A=g_AO, B=g_Wp -> +bias, store out (b,o,n) fp32
// ---------------------------------------------------------------------------
__device__ __forceinline__ void load_tile_pair(uint32_t sbase,
                                               const char* pA, const char* pB,
                                               int kB, int tid)
{
#pragma unroll
    for (int half = 0; half < 2; half++) {
        const uint32_t tb = sbase + half * HSTEP;
        const int kOfs = kB + half * 64;
#pragma unroll
        for (int t = 0; t < 2; t++) {
            const int i = t * 256 + tid;
            const int row = i >> 2, c = i & 3;
            const uint32_t off = tile_off(row, c);
            const size_t g = (size_t)row * (C_ * 2) + kOfs + c * 16;
            cp16(tb + OFF_A + off, pA + g);
            cp16(tb + OFF_B + off, pB + g);
        }
    }
    cp_commit();
}

__device__ __forceinline__ void compute_chunk(uint32_t base,
                                              const uint32_t aoff[2][2],
                                              const uint32_t boff[2][4],
                                              float acc[2][8][4])
{
#pragma unroll
    for (int kk = 0; kk < 2; kk++) {
        uint32_t ah[2][4], bh[4][4];
#pragma unroll
        for (int mi = 0; mi < 2; mi++)
            ldm_x4(ah[mi], base + aoff[kk][mi]);
#pragma unroll
        for (int nj4 = 0; nj4 < 4; nj4++)
            ldm_x4(bh[nj4], base + boff[kk][nj4]);
#pragma unroll
        for (int mi = 0; mi < 2; mi++)
#pragma unroll
            for (int nj = 0; nj < 8; nj++) {
                const int g = nj >> 1, p = nj & 1;
                mma16816(acc[mi][nj], ah[mi], bh[g][p], bh[g][p + 2]);
            }
    }
}

template <int MODE>
__global__ __launch_bounds__(256, 2) void gemm_kernel(const float* __restrict__ bias,
                                                      float* __restrict__ out)
{
    extern __shared__ char sm[];
    const uint32_t sb = smem_u32(sm);
    const int tid = threadIdx.x, lane = tid & 31, wid = tid >> 5;
    const int wm = wid >> 1, wn = wid & 1;
    const int b = blockIdx.z, m0 = blockIdx.y * 128, o0 = blockIdx.x * 128;

    const __half* A = (MODE == 0) ? g_X : g_AO;
    const __half* Bw = (MODE == 0) ? g_Wq : g_Wp;

    const char* pA = (const char*)(A + ((size_t)b * N_ + m0) * C_);
    const char* pB = (const char*)(Bw + (size_t)o0 * C_);

    // hoisted fragment offsets (invariant across stages/halves)
    const int ldrow = lane & 15, ldc = lane >> 4;
    uint32_t aoff[2][2], boff[2][4];
#pragma unroll
    for (int kk = 0; kk < 2; kk++) {
        const int c = kk * 2 + ldc;
#pragma unroll
        for (int mi = 0; mi < 2; mi++)
            aoff[kk][mi] = OFF_A + tile_off(wm * 32 + mi * 16 + ldrow, c);
#pragma unroll
        for (int nj4 = 0; nj4 < 4; nj4++)
            boff[kk][nj4] = OFF_B + tile_off(wn * 64 + nj4 * 16 + ldrow, c);
    }

    float acc[2][8][4] = {};

    // prologue: 2 stages in flight
    load_tile_pair(sb + 0 * STAGE, pA, pB, 0, tid);
    load_tile_pair(sb + 1 * STAGE, pA, pB, 128, tid);

    int bufIdx = 0;
#pragma unroll 1
    for (int st = 0; st < 6; st++) {
        if (st + 2 < 6) {
            const int nb = (bufIdx + 2 >= NSTG) ? bufIdx + 2 - NSTG : bufIdx + 2;
            load_tile_pair(sb + nb * STAGE, pA, pB, (st + 2) * 128, tid);
            cp_wait<2>();
        } else if (st + 2 == 6) {
            cp_wait<1>();
        } else {
            cp_wait<0>();
        }
        __syncthreads();
        const uint32_t base = sb + bufIdx * STAGE;
        compute_chunk(base, aoff, boff, acc);
        compute_chunk(base + HSTEP, aoff, boff, acc);
        __syncthreads();
        bufIdx = (bufIdx + 1 >= NSTG) ? 0 : bufIdx + 1;
    }

    if (MODE == 0) {
#pragma unroll
        for (int mi = 0; mi < 2; mi++) {
            const int m = m0 + wm * 32 + mi * 16 + (lane >> 2);
#pragma unroll
            for (int nj = 0; nj < 8; nj++) {
                const int o = o0 + wn * 64 + nj * 8 + (lane & 3) * 2;
                const int s = o / C_;
                const int rem = o - s * C_;
                const int h = rem >> 5, d = rem & 31;
                __half* base = (s == 0) ? g_Q : (s == 1) ? g_K : g_V;
                const float b0 = bias[o], b1 = bias[o + 1];
                __half* p0 = base + ((size_t)(b * NH + h) * N_ + m) * HD + d;
                *(uint32_t*)p0 = pack2h(acc[mi][nj][0] + b0, acc[mi][nj][1] + b1);
                *(uint32_t*)(p0 + 8 * HD) = pack2h(acc[mi][nj][2] + b0, acc[mi][nj][3] + b1);
            }
        }
    } else {
        float* ob = out + (size_t)b * C_ * N_;
#pragma unroll
        for (int mi = 0; mi < 2; mi++) {
            const int m = m0 + wm * 32 + mi * 16 + (lane >> 2);
#pragma unroll
            for (int nj = 0; nj < 8; nj++) {
                const int o = o0 + wn * 64 + nj * 8 + (lane & 3) * 2;
                const float b0 = bias[o], b1 = bias[o + 1];
                ob[(size_t)o * N_ + m]           = acc[mi][nj][0] + b0;
                ob[(size_t)(o + 1) * N_ + m]     = acc[mi][nj][1] + b1;
                ob[(size_t)o * N_ + m + 8]       = acc[mi][nj][2] + b0;
                ob[(size_t)(o + 1) * N_ + m + 8] = acc[mi][nj][3] + b1;
            }
        }
    }
}

// ---------------------------------------------------------------------------
// Tensor-core attention, single fp16. One CTA per (b,h), 8 warps x 32 q-rows.
// Q pre-scaled by SCALE*log2(e): E = 2^S via bare ex2 (no FMUL).
// |s| small (normalized q,k): no max-subtraction; clip provably inactive.
// rowsum(E) via ones-MMA. O += E V. O /= rowsum.
// ---------------------------------------------------------------------------
#define SQ 0
#define SK 16384
#define SV 32768
#define SM_ATT 49152

__global__ __launch_bounds__(256, 2) void attn_tc_kernel()
{
    extern __shared__ char sma[];
    const uint32_t sb = smem_u32(sma);
    const int bh = blockIdx.x, tid = threadIdx.x, lane = tid & 31, wid = tid >> 5;

    const __half* Qg = g_Q + (size_t)bh * (N_ * HD);
    const __half* Kg = g_K + (size_t)bh * (N_ * HD);
    const __half* Vg = g_V + (size_t)bh * (N_ * HD);

    // ---- prep: 1 row / thread into swizzled smem ----
    {
        // V: raw copy (already fp16)
        uint4 raw[4];
#pragma unroll
        for (int c = 0; c < 4; c++) raw[c] = ((const uint4*)(Vg + tid * HD))[c];
#pragma unroll
        for (int c = 0; c < 4; c++) {
            const uint32_t off = off256(tid, c);
            asm volatile("st.shared.v4.b32 [%0], {%1,%2,%3,%4};"
                         :: "r"(sb + SV + off), "r"(raw[c].x), "r"(raw[c].y),
                            "r"(raw[c].z), "r"(raw[c].w));
        }
        // K: normalize
#pragma unroll
        for (int c = 0; c < 4; c++) raw[c] = ((const uint4*)(Kg + tid * HD))[c];
        {
            const __half2* h2 = (const __half2*)raw;
            float2 f[16];
            float ss = 0.f;
#pragma unroll
            for (int j = 0; j < 16; j++) {
                f[j] = __half22float2(h2[j]);
                ss += f[j].x * f[j].x + f[j].y * f[j].y;
            }
            const float inv = 1.f / fmaxf(sqrtf(ss), 1e-12f);
#pragma unroll
            for (int c = 0; c < 4; c++) {
                uint32_t w0 = pack2h(f[c * 4 + 0].x * inv, f[c * 4 + 0].y * inv);
                uint32_t w1 = pack2h(f[c * 4 + 1].x * inv, f[c * 4 + 1].y * inv);
                uint32_t w2 = pack2h(f[c * 4 + 2].x * inv, f[c * 4 + 2].y * inv);
                uint32_t w3 = pack2h(f[c * 4 + 3].x * inv, f[c * 4 + 3].y * inv);
                const uint32_t off = off256(tid, c);
                asm volatile("st.shared.v4.b32 [%0], {%1,%2,%3,%4};"
                             :: "r"(sb + SK + off), "r"(w0), "r"(w1), "r"(w2), "r"(w3));
            }
        }
        // Q: normalize * SCALE * log2(e)
#pragma unroll
        for (int c = 0; c < 4; c++) raw[c] = ((const uint4*)(Qg + tid * HD))[c];
        {
            const __half2* h2 = (const __half2*)raw;
            float2 f[16];
            float ss = 0.f;
#pragma unroll
            for (int j = 0; j < 16; j++) {
                f[j] = __half22float2(h2[j]);
                ss += f[j].x * f[j].x + f[j].y * f[j].y;
            }
            const float inv = kQS / fmaxf(sqrtf(ss), 1e-12f);
#pragma unroll
            for (int c = 0; c < 4; c++) {
                uint32_t w0 = pack2h(f[c * 4 + 0].x * inv, f[c * 4 + 0].y * inv);
                uint32_t w1 = pack2h(f[c * 4 + 1].x * inv, f[c * 4 + 1].y * inv);
                uint32_t w2 = pack2h(f[c * 4 + 2].x * inv, f[c * 4 + 2].y * inv);
                uint32_t w3 = pack2h(f[c * 4 + 3].x * inv, f[c * 4 + 3].y * inv);
                const uint32_t off = off256(tid, c);
                asm volatile("st.shared.v4.b32 [%0], {%1,%2,%3,%4};"
                             :: "r"(sb + SQ + off), "r"(w0), "r"(w1), "r"(w2), "r"(w3));
            }
        }
    }
    __syncthreads();

    // ---- Q fragments (held for whole kernel) ----
    const int m0 = wid * 32;
    const int ldrow = lane & 15, ldc = lane >> 4;
    uint32_t qh[2][2][4];
#pragma unroll
    for (int mi = 0; mi < 2; mi++)
#pragma unroll
        for (int kk = 0; kk < 2; kk++)
            ldm_x4(qh[mi][kk], sb + SQ + off256(m0 + mi * 16 + ldrow, kk * 2 + ldc));

    float O[2][4][4] = {};
    float rsO[2][4] = {};   // ones-MMA rowsum accumulator

    // precomputed fragment base addresses; per-chunk delta is
    // (ch&3)*2048 + (ch>>2)*8192 (swizzle invariant under row+32)
    uint32_t kbase[2][2], vbase[2][2];
    const int vrow = (lane & 7) + (((lane >> 4) & 1) << 3);
    const int vcsel = (lane >> 3) & 1;
#pragma unroll
    for (int g = 0; g < 2; g++)
#pragma unroll
        for (int kk = 0; kk < 2; kk++)
            kbase[g][kk] = sb + SK + off256(g * 16 + ldrow, kk * 2 + ldc);
#pragma unroll
    for (int t16 = 0; t16 < 2; t16++)
#pragma unroll
        for (int j = 0; j < 2; j++)
            vbase[t16][j] = sb + SV + off256(t16 * 16 + vrow, j * 2 + vcsel);

#pragma unroll 1
    for (int ch = 0; ch < 8; ch++) {
        const uint32_t choff = ((uint32_t)(ch & 3) << 11) + ((uint32_t)(ch >> 2) << 13);

        uint32_t kh[2][2][4];
#pragma unroll
        for (int g = 0; g < 2; g++)
#pragma unroll
            for (int kk = 0; kk < 2; kk++)
                ldm_x4(kh[g][kk], kbase[g][kk] + choff);

        float S[2][4][4] = {};
#pragma unroll
        for (int kk = 0; kk < 2; kk++)
#pragma unroll
            for (int mi = 0; mi < 2; mi++)
#pragma unroll
                for (int nj = 0; nj < 4; nj++) {
                    const int g = nj >> 1, p = nj & 1;
                    mma16816(S[mi][nj], qh[mi][kk], kh[g][kk][p], kh[g][kk][p + 2]);
                }

        // E = 2^S (bare ex2); repack C-frag -> A-frag (single fp16)
        uint32_t eh[2][2][4];
#pragma unroll
        for (int mi = 0; mi < 2; mi++)
#pragma unroll
            for (int t = 0; t < 2; t++) {
                float e0 = ex2f(S[mi][2 * t][0]);
                float e1 = ex2f(S[mi][2 * t][1]);
                float e2 = ex2f(S[mi][2 * t][2]);
                float e3 = ex2f(S[mi][2 * t][3]);
                float f0 = ex2f(S[mi][2 * t + 1][0]);
                float f1 = ex2f(S[mi][2 * t + 1][1]);
                float f2 = ex2f(S[mi][2 * t + 1][2]);
                float f3 = ex2f(S[mi][2 * t + 1][3]);
                eh[mi][t][0] = pack2h(e0, e1);
                eh[mi][t][1] = pack2h(e2, e3);
                eh[mi][t][2] = pack2h(f0, f1);
                eh[mi][t][3] = pack2h(f2, f3);
            }

        uint32_t vh[2][2][4];
#pragma unroll
        for (int t16 = 0; t16 < 2; t16++)
#pragma unroll
            for (int j = 0; j < 2; j++)
                ldm_x4_t(vh[t16][j], vbase[t16][j] + choff);

#pragma unroll
        for (int t16 = 0; t16 < 2; t16++)
#pragma unroll
            for (int mi = 0; mi < 2; mi++) {
                mma16816(rsO[mi], eh[mi][t16], ONES2H, ONES2H);
#pragma unroll
                for (int nd = 0; nd < 4; nd++) {
                    const int j = nd >> 1, p = nd & 1;
                    mma16816(O[mi][nd], eh[mi][t16], vh[t16][j][p], vh[t16][j][p + 2]);
                }
            }
    }

    // ---- divide by rowsum, store fp16 ----
    const int b = bh / NH, h = bh - (bh / NH) * NH;
#pragma unroll
    for (int mi = 0; mi < 2; mi++) {
        const float i0 = 1.f / rsO[mi][0];
        const float i1 = 1.f / rsO[mi][2];
        const int r1 = m0 + mi * 16 + (lane >> 2);
        const int r2 = r1 + 8;
#pragma unroll
        for (int nd = 0; nd < 4; nd++) {
            const int col = h * HD + nd * 8 + (lane & 3) * 2;
            const size_t a1 = ((size_t)b * N_ + r1) * C_ + col;
            const size_t a2 = ((size_t)b * N_ + r2) * C_ + col;
            *(uint32_t*)(g_AO + a1) = pack2h(O[mi][nd][0] * i0, O[mi][nd][1] * i0);
            *(uint32_t*)(g_AO + a2) = pack2h(O[mi][nd][2] * i1, O[mi][nd][3] * i1);
        }
    }
}

// ---------------------------------------------------------------------------
extern "C" void kernel_launch(void* const* d_in, const int* in_sizes, int n_in,
                              void* d_out, int out_size)
{
    const float* x      = (const float*)d_in[0];
    const float* qkv_w  = (const float*)d_in[1];
    const float* qkv_b  = (const float*)d_in[2];
    const float* proj_w = (const float*)d_in[3];
    const float* proj_b = (const float*)d_in[4];
    float* out = (float*)d_out;

    cudaFuncSetAttribute(gemm_kernel<0>, cudaFuncAttributeMaxDynamicSharedMemorySize, SM_TOTAL);
    cudaFuncSetAttribute(gemm_kernel<1>, cudaFuncAttributeMaxDynamicSharedMemorySize, SM_TOTAL);
    cudaFuncSetAttribute(attn_tc_kernel, cudaFuncAttributeMaxDynamicSharedMemorySize, SM_ATT);

    const int wblocks = (H3 * C_ + C_ * C_ + 255) / 256;
    convert_all<<<XBLOCKS + wblocks, 256>>>(x, qkv_w, proj_w);
    gemm_kernel<0><<<dim3(H3 / 128, N_ / 128, B_), 256, SM_TOTAL>>>(qkv_b, nullptr);
    attn_tc_kernel<<<B_ * NH, 256, SM_ATT>>>();
    gemm_kernel<1><<<dim3(C_ / 128, N_ / 128, B_), 256, SM_TOTAL>>>(proj_b, out);
}